// round 16
// baseline (speedup 1.0000x reference)
#include <cuda_runtime.h>
#include <cuda_fp16.h>
#include <cstdint>
#include <math.h>

// Problem constants
#define B_  16
#define C_  64
#define H_  192
#define W_  192
#define H2_ 64
#define W2_ 64
#define S_  5

// ---------------------------------------------------------------------------
// Scratch buffers (static device globals; zero-initialized at load)
// ---------------------------------------------------------------------------
__device__ float g_attnP[2][B_ * C_ * C_ * S_ * S_];  // 2 K-half partials
__device__ float g_ak[B_ * C_ * C_ * 9];              // transposed ak (pre-norm)

// fp16 operands (all single precision; fp32 staging between stages).
__device__ __align__(16) __half g_x_hi[B_ * H_ * W_ * C_];  // channel-last
__device__ __align__(16) __half g_kt[B_ * 9 * C_ * C_];     // [b][tap][oc][ci]
__device__ __align__(16) __half g_wq[2 * 9 * 64 * 64];      // [half][tap][oc][ci]
__device__ __align__(16) __half g_w16[64 * 576];            // weight fp16 linear [cB][ci*9+d9]
// attn A operand: k channel-major [b][co][4096]
__device__ __align__(16) __half g_k1[B_ * C_ * 4096];
// attn B operand: q shifted copies [dj(5)][b][ci][68 rows (zero-pad)][64]
__device__ __align__(16) __half g_q5[5 * B_ * C_ * 68 * 64];

__device__ __forceinline__ uint32_t smem_u32(const void* p) {
    uint32_t a;
    asm("{ .reg .u64 t; cvta.to.shared.u64 t, %1; cvt.u32.u64 %0, t; }" : "=r"(a) : "l"(p));
    return a;
}

__device__ __forceinline__ void ldsm_x4(uint32_t* r, uint32_t addr) {
    asm volatile("ldmatrix.sync.aligned.m8n8.x4.shared.b16 {%0,%1,%2,%3}, [%4];"
                 : "=r"(r[0]), "=r"(r[1]), "=r"(r[2]), "=r"(r[3])
                 : "r"(addr));
}

// mma.sync m16n8k16 fp16 -> fp32 accum (in-place)
__device__ __forceinline__ void mma_fp16(float* d, const uint32_t* a, const uint32_t* b) {
    asm volatile(
        "mma.sync.aligned.m16n8k16.row.col.f32.f16.f16.f32 "
        "{%0,%1,%2,%3}, {%4,%5,%6,%7}, {%8,%9}, {%0,%1,%2,%3};"
        : "+f"(d[0]), "+f"(d[1]), "+f"(d[2]), "+f"(d[3])
        : "r"(a[0]), "r"(a[1]), "r"(a[2]), "r"(a[3]), "r"(b[0]), "r"(b[1]));
}

#define CP16(dst, src) \
    asm volatile("cp.async.cg.shared.global [%0], [%1], 16;" ::"r"(dst), "l"(src))
#define CP_COMMIT() asm volatile("cp.async.commit_group;" ::: "memory")
#define CP_WAIT(N) asm volatile("cp.async.wait_group %0;" ::"n"(N) : "memory")

// ---------------------------------------------------------------------------
// Kernel E0: x (fp32 NCHW) -> channel-last fp16; b==16 repacks w_qk and weight.
// ---------------------------------------------------------------------------
__global__ void __launch_bounds__(256) xcl_kernel(const float* __restrict__ x,
                                                  const float* __restrict__ w_qk,
                                                  const float* __restrict__ wgt) {
    const int seg = blockIdx.x;
    const int b = blockIdx.y;
    const int tid = threadIdx.x;

    if (b == 16) {
        if (seg < 128) {
            const int half = seg >> 6, oc = seg & 63;
            for (int t = tid; t < 576; t += 256) {
                int ci = t / 9, tap = t % 9;
                g_wq[((half * 9 + tap) * 64 + oc) * 64 + ci] =
                    __float2half(w_qk[(seg * 64 + ci) * 9 + tap]);
            }
        } else if (seg < 192) {
            const int cB = seg - 128;
            for (int t = tid; t < 576; t += 256)
                g_w16[cB * 576 + t] = __float2half(wgt[cB * 576 + t]);
        }
        return;
    }

    const int y = seg / 3;
    const int x0 = (seg % 3) * 64;
    __shared__ float s[64][65];

#pragma unroll
    for (int i = 0; i < 16; ++i) {
        int idx = tid + i * 256;
        int c = idx >> 6, p = idx & 63;
        s[p][c] = x[((b * 64 + c) * 192 + y) * 192 + x0 + p];
    }
    __syncthreads();
#pragma unroll
    for (int i = 0; i < 16; ++i) {
        int idx = tid + i * 256;
        int p = idx >> 6, c = idx & 63;
        g_x_hi[((b * 192 + y) * 192 + x0 + p) * 64 + c] = __float2half(s[p][c]);
    }
}

// ---------------------------------------------------------------------------
// Kernel A: qk conv via mma.sync (stride-3), cp.async tap double-buffer.
// FUSED epilogue: k -> g_k1, q -> g_q5 (5 dj copies).
// grid (32 mtiles, 2 half, 16 b), 128 thr. smem 2 x 24KB.
// ---------------------------------------------------------------------------
#define QK_B    16384
#define QK_BUF  24576
#define QK_TOT  49152

__global__ void __launch_bounds__(128) qk_mma_kernel() {
    extern __shared__ char smem[];
    const int mtile = blockIdx.x, half = blockIdx.y, b = blockIdx.z;
    const int i0 = mtile * 2;
    const int tid = threadIdx.x, wid = tid >> 5, lid = tid & 31;
    const uint32_t sbase = smem_u32(smem);

    const int r = tid;
    const int ri = i0 + (r >> 6), rj = r & 63;

    float acc[2][8][4];
#pragma unroll
    for (int mt = 0; mt < 2; ++mt)
#pragma unroll
        for (int j = 0; j < 8; ++j)
#pragma unroll
            for (int e = 0; e < 4; ++e) acc[mt][j][e] = 0.f;

    const int arow0 = wid * 32 + (lid & 15);
    const int apart = lid >> 4;
    const int brow0 = (lid & 7) + ((lid >> 4) << 3);
    const int bpart = (lid >> 3) & 1;

    auto prefetch = [&](int tap, int bi) {
        uint32_t sb = sbase + (uint32_t)bi * QK_BUF;
        const int dy = tap / 3, dx = tap % 3;
        long abase = ((long)(b * 192 + 3 * ri + dy) * 192 + 3 * rj + dx) * 8;
        const uint4* sh = (const uint4*)g_x_hi + abase;
#pragma unroll
        for (int c = 0; c < 8; ++c) {
            uint32_t off = (uint32_t)r * 128u + (uint32_t)((c ^ (r & 7)) << 4);
            CP16(sb + off, sh + c);
        }
        const uint4* wp = (const uint4*)g_wq + (half * 9 + tap) * 512;
#pragma unroll
        for (int i = 0; i < 4; ++i) {
            int idx = tid + i * 128;
            int row = idx >> 3, c = idx & 7;
            uint32_t off = (uint32_t)row * 128u + (uint32_t)((c ^ (row & 7)) << 4);
            CP16(sb + QK_B + off, wp + idx);
        }
    };

    prefetch(0, 0);
    CP_COMMIT();

    for (int tap = 0; tap < 9; ++tap) {
        if (tap < 8) {
            prefetch(tap + 1, (tap + 1) & 1);
            CP_COMMIT();
            CP_WAIT(1);
        } else {
            CP_WAIT(0);
        }
        __syncthreads();

        const uint32_t sb = sbase + (uint32_t)(tap & 1) * QK_BUF;
#pragma unroll
        for (int kc = 0; kc < 4; ++kc) {
            const int acol = kc * 2 + apart;
            const int bcol = kc * 2 + bpart;
            uint32_t bf[4][4], ah[2][4];
#pragma unroll
            for (int nt = 0; nt < 4; ++nt) {
                int row = brow0 + nt * 16;
                ldsm_x4(bf[nt], sb + QK_B + row * 128 + ((bcol ^ (row & 7)) << 4));
            }
#pragma unroll
            for (int mt = 0; mt < 2; ++mt) {
                int row = arow0 + mt * 16;
                ldsm_x4(ah[mt], sb + row * 128 + ((acol ^ (row & 7)) << 4));
            }
#pragma unroll
            for (int mt = 0; mt < 2; ++mt)
#pragma unroll
                for (int j = 0; j < 8; ++j)
                    mma_fp16(acc[mt][j], ah[mt], &bf[j >> 1][2 * (j & 1)]);
        }
        __syncthreads();
    }

    // ---- fused epilogue: stage fp32 [m][ch] (stride 65), emit fp16 operands
    float* st = (float*)smem;
#pragma unroll
    for (int mt = 0; mt < 2; ++mt)
#pragma unroll
        for (int j = 0; j < 8; ++j)
#pragma unroll
            for (int e = 0; e < 4; ++e) {
                int m = wid * 32 + mt * 16 + (lid >> 2) + ((e >> 1) << 3);
                int col = j * 8 + (lid & 3) * 2 + (e & 1);
                st[m * 65 + col] = acc[mt][j][e];
            }
    __syncthreads();

    if (half) {
        for (int t = tid; t < 8192; t += 128) {
            int co = t >> 7, m = t & 127;
            int h = i0 + (m >> 6), w = m & 63;
            long o = (long)(b * 64 + co) * 4096 + h * 64 + w;
            g_k1[o] = __float2half(st[m * 65 + co]);
        }
    } else {
        for (int dj = 0; dj < 5; ++dj) {
            for (int t = tid; t < 8192; t += 128) {
                int ci = t >> 7, m = t & 127;
                int h = i0 + (m >> 6), w = m & 63;
                int wsrc = w + dj - 2;
                float v = ((unsigned)wsrc < 64u) ? st[((m >> 6) * 64 + wsrc) * 65 + ci] : 0.f;
                long o = (((long)(dj * 16 + b) * 64 + ci) * 68 + (h + 2)) * 64 + w;
                g_q5[o] = __float2half(v);
            }
        }
    }
}

// ---------------------------------------------------------------------------
// Kernel B: attn via mma.sync, K SPLIT IN 2. grid (25, 2, 16), 128 thr.
// ---------------------------------------------------------------------------
#define AT_Q   8192
#define AT_BUF 16384
#define AT_TOT 32768

__global__ void __launch_bounds__(128) attn_mma_kernel() {
    extern __shared__ char smem[];
    const int dj = blockIdx.x % 5, di = blockIdx.x / 5;
    const int half = blockIdx.y, b = blockIdx.z;
    const int tid = threadIdx.x, wid = tid >> 5, lid = tid & 31;
    const uint32_t sbase = smem_u32(smem);
    const int mrow = (wid & 1) * 32, ncol = (wid >> 1) * 32;

    float acc[2][4][4];
#pragma unroll
    for (int mt = 0; mt < 2; ++mt)
#pragma unroll
        for (int j = 0; j < 4; ++j)
#pragma unroll
            for (int e = 0; e < 4; ++e) acc[mt][j][e] = 0.f;

    const uint4* __restrict__ kp = (const uint4*)g_k1 + (long)b * 64 * 512;
    const uint4* __restrict__ qp = (const uint4*)g_q5 + (long)(dj * 16 + b) * 64 * 544 + di * 8;

    const int apart = lid >> 4;
    const int brow_l = (lid & 7) + ((lid >> 4) << 3);
    const int bpart = (lid >> 3) & 1;
    const int kc0 = half * 32;

    auto prefetch = [&](int kc, int bi) {
        uint32_t sb = sbase + (uint32_t)bi * AT_BUF;
#pragma unroll
        for (int a = 0; a < 2; ++a) {
            const uint4* gp = (a == 0) ? kp : qp;
            const int stride = (a == 0) ? 512 : 544;
#pragma unroll
            for (int u = 0; u < 4; ++u) {
                int idx = tid + u * 128;
                int row = idx >> 3, c = idx & 7;
                uint32_t off = (uint32_t)a * 8192u + (uint32_t)row * 128u +
                               (uint32_t)((c ^ (row & 7)) << 4);
                CP16(sb + off, gp + (long)row * stride + kc * 8 + c);
            }
        }
    };

    prefetch(kc0, 0);
    CP_COMMIT();

    for (int kc2 = 0; kc2 < 32; ++kc2) {
        if (kc2 < 31) {
            prefetch(kc0 + kc2 + 1, (kc2 + 1) & 1);
            CP_COMMIT();
            CP_WAIT(1);
        } else {
            CP_WAIT(0);
        }
        __syncthreads();

        const uint32_t sb = sbase + (uint32_t)(kc2 & 1) * AT_BUF;
#pragma unroll
        for (int kk = 0; kk < 4; ++kk) {
            uint32_t ah[2][4], bh[2][4];
            const int acol = kk * 2 + apart;
            const int bcol = kk * 2 + bpart;
#pragma unroll
            for (int mt = 0; mt < 2; ++mt) {
                int row = mrow + mt * 16 + (lid & 15);
                ldsm_x4(ah[mt], sb + row * 128 + ((acol ^ (row & 7)) << 4));
            }
#pragma unroll
            for (int nt = 0; nt < 2; ++nt) {
                int row = ncol + nt * 16 + brow_l;
                ldsm_x4(bh[nt], sb + AT_Q + row * 128 + ((bcol ^ (row & 7)) << 4));
            }
#pragma unroll
            for (int mt = 0; mt < 2; ++mt)
#pragma unroll
                for (int j = 0; j < 4; ++j)
                    mma_fp16(acc[mt][j], ah[mt], &bh[j >> 1][2 * (j & 1)]);
        }
        __syncthreads();
    }

    float* dst = g_attnP[half];
#pragma unroll
    for (int mt = 0; mt < 2; ++mt)
#pragma unroll
        for (int j = 0; j < 4; ++j)
#pragma unroll
            for (int e = 0; e < 4; ++e) {
                int co = mrow + mt * 16 + (lid >> 2) + ((e >> 1) << 3);
                int ci = ncol + j * 8 + (lid & 3) * 2 + (e & 1);
                dst[((b * 64 + co) * 64 + ci) * 25 + di * 5 + dj] = acc[mt][j][e];
            }
}

// ---------------------------------------------------------------------------
// Kernel C1: ak conv AS GEMM. Per (t,b): ak[cB][cA][t] = A(w) x B(attn-gather),
// M=64(cB), N=64(cA), K=576 (ci*9+d9). A = g_w16 (cp.async); B gathered from
// g_attnP sum with per-t tap shift, converted fp16 at fill.
// grid (9 t, 16 b), 128 thr, smem 2 x (A 8K | B 8K) = 32KB.
// ---------------------------------------------------------------------------
#define AK_B    8192
#define AK_BUF  16384

__global__ void __launch_bounds__(128) akconv_mma_kernel() {
    extern __shared__ char smem[];
    const int t = blockIdx.x, b = blockIdx.y;
    const int tid = threadIdx.x, wid = tid >> 5, lid = tid & 31;
    const uint32_t sbase = smem_u32(smem);
    const int mrow = (wid & 1) * 32, ncol = (wid >> 1) * 32;
    const int ty = t / 3, tx = t % 3;

    int offT[9];
#pragma unroll
    for (int d9 = 0; d9 < 9; ++d9)
        offT[d9] = (ty + d9 / 3) * 5 + tx + d9 % 3;

    float acc[2][4][4];
#pragma unroll
    for (int mt = 0; mt < 2; ++mt)
#pragma unroll
        for (int j = 0; j < 4; ++j)
#pragma unroll
            for (int e = 0; e < 4; ++e) acc[mt][j][e] = 0.f;

    const int apart = lid >> 4;
    const int brow_l = (lid & 7) + ((lid >> 4) << 3);
    const int bpart = (lid >> 3) & 1;

    // A chunk via cp.async: rows cB, 64 k = 128B; w16 row stride 576h = 72 uint4
    auto prefA = [&](int kc, int bi) {
        uint32_t sb = sbase + (uint32_t)bi * AK_BUF;
        const uint4* wp = (const uint4*)g_w16;
#pragma unroll
        for (int u = 0; u < 4; ++u) {
            int idx = tid + u * 128;
            int row = idx >> 3, c = idx & 7;
            uint32_t off = (uint32_t)row * 128u + (uint32_t)((c ^ (row & 7)) << 4);
            CP16(sb + off, wp + (long)row * 72 + kc * 8 + c);
        }
    };
    // B chunk via gather+convert: row cA, col k-kc*64
    auto fillB = [&](int kc, int bi) {
        uint32_t sb = sbase + (uint32_t)bi * AK_BUF + AK_B;
#pragma unroll 4
        for (int i = 0; i < 32; ++i) {
            int idx = tid + i * 128;  // 0..4095
            int cA = idx >> 6, col = idx & 63;
            int k = kc * 64 + col;
            int ci = k / 9, d9 = k - ci * 9;
            long o = ((long)(b * 64 + cA) * 64 + ci) * 25 + offT[d9];
            float v = g_attnP[0][o] + g_attnP[1][o];
            uint32_t c16 = col >> 3;
            uint32_t boff = (uint32_t)cA * 128u + ((c16 ^ (cA & 7)) << 4) + ((col & 7) << 1);
            *(__half*)(smem + sb - sbase + boff) = __float2half(v);
        }
    };

    prefA(0, 0);
    CP_COMMIT();
    fillB(0, 0);
    CP_WAIT(0);
    __syncthreads();

    for (int kc = 0; kc < 9; ++kc) {
        const int nb = (kc + 1) & 1;
        if (kc < 8) {
            prefA(kc + 1, nb);
            CP_COMMIT();
            fillB(kc + 1, nb);
        }

        const uint32_t sb = sbase + (uint32_t)(kc & 1) * AK_BUF;
#pragma unroll
        for (int kk = 0; kk < 4; ++kk) {
            uint32_t ah[2][4], bh[2][4];
            const int acol = kk * 2 + apart;
            const int bcol = kk * 2 + bpart;
#pragma unroll
            for (int mt = 0; mt < 2; ++mt) {
                int row = mrow + mt * 16 + (lid & 15);
                ldsm_x4(ah[mt], sb + row * 128 + ((acol ^ (row & 7)) << 4));
            }
#pragma unroll
            for (int nt = 0; nt < 2; ++nt) {
                int row = ncol + nt * 16 + brow_l;
                ldsm_x4(bh[nt], sb + AK_B + row * 128 + ((bcol ^ (row & 7)) << 4));
            }
#pragma unroll
            for (int mt = 0; mt < 2; ++mt)
#pragma unroll
                for (int j = 0; j < 4; ++j)
                    mma_fp16(acc[mt][j], ah[mt], &bh[j >> 1][2 * (j & 1)]);
        }
        CP_WAIT(0);
        __syncthreads();
    }

#pragma unroll
    for (int mt = 0; mt < 2; ++mt)
#pragma unroll
        for (int j = 0; j < 4; ++j)
#pragma unroll
            for (int e = 0; e < 4; ++e) {
                int cB = mrow + mt * 16 + (lid >> 2) + ((e >> 1) << 3);
                int cA = ncol + j * 8 + (lid & 3) * 2 + (e & 1);
                g_ak[((b * 64 + cB) * 64 + cA) * 9 + t] = acc[mt][j][e];
            }
}

// ---------------------------------------------------------------------------
// Kernel C2: normalize ak, build dynamic kernels -> single fp16 B tiles
// ---------------------------------------------------------------------------
__global__ void __launch_bounds__(64) kern_kernel(const float* __restrict__ weight,
                                                  const float* __restrict__ temperature) {
    const int cB  = blockIdx.x;
    const int b   = blockIdx.y;
    const int tid = threadIdx.x;  // = cA

    const float* ak = g_ak + (b * 64 + cB) * 64 * 9;
    float v[9];
    float ss = 0.f;
#pragma unroll
    for (int t9 = 0; t9 < 9; ++t9) {
        v[t9] = ak[tid * 9 + t9];
        ss = fmaf(v[t9], v[t9], ss);
    }

    __shared__ float red[64];
    red[tid] = ss;
    __syncthreads();
#pragma unroll
    for (int s = 32; s >= 1; s >>= 1) {
        if (tid < s) red[tid] += red[tid + s];
        __syncthreads();
    }
    float nrm = sqrtf(red[0]);
    float scale = temperature[0] / fmaxf(nrm, 1e-12f);

#pragma unroll
    for (int t9 = 0; t9 < 9; ++t9) {
        float vv = weight[(cB * 64 + tid) * 9 + t9] + v[t9] * scale;
        g_kt[((b * 9 + t9) * 64 + cB) * 64 + tid] = __float2half(vv);
    }
}

// ---------------------------------------------------------------------------
// Kernel D: final conv via mma.sync, M=256 (8y x 32x), 128 thr, warp m=64.
// smem: A halo 340x128=43520 | B 2x8192; epilogue needs 256*65*4=66560.
// ---------------------------------------------------------------------------
#define DB     43520
#define D_TOT  66560

__global__ void __launch_bounds__(128) final_mma_kernel(float* __restrict__ out) {
    extern __shared__ char smem[];
    const int xt = blockIdx.x, yp = blockIdx.y, b = blockIdx.z;
    const int x0 = xt * 32, y0 = yp * 8;
    const int tid = threadIdx.x, wid = tid >> 5, lid = tid & 31;
    const uint32_t sbase = smem_u32(smem);

    float acc[4][8][4];
#pragma unroll
    for (int mt = 0; mt < 4; ++mt)
#pragma unroll
        for (int j = 0; j < 8; ++j)
#pragma unroll
            for (int e = 0; e < 4; ++e) acc[mt][j][e] = 0.f;

    const int apart = lid >> 4;
    const int brow0 = (lid & 7) + ((lid >> 4) << 3);
    const int bpart = (lid >> 3) & 1;
    int hra[4];
#pragma unroll
    for (int mt = 0; mt < 4; ++mt) {
        int m = wid * 64 + mt * 16 + (lid & 15);
        hra[mt] = ((m >> 5) + 1) * 34 + (m & 31) + 1;
    }

    auto prefetchB = [&](int tap, int bi) {
        uint32_t sb = sbase + DB + (uint32_t)bi * 8192u;
        const uint4* kp = (const uint4*)g_kt + (b * 9 + tap) * 512;
#pragma unroll
        for (int u = 0; u < 4; ++u) {
            int idx = tid + u * 128;
            int row = idx >> 3, c = idx & 7;
            uint32_t off = (uint32_t)row * 128u + (uint32_t)((c ^ (row & 7)) << 4);
            CP16(sb + off, kp + idx);
        }
    };

    // ---- one-time A halo fill (340 rows = 10y x 34x) + B tap0 ----
    for (int hr = tid; hr < 340; hr += 128) {
        int hy = hr / 34, hx = hr % 34;
        int y = y0 - 1 + hy, xg = x0 - 1 + hx;
        bool ok = ((unsigned)y < (unsigned)H_) && ((unsigned)xg < (unsigned)W_);
        long base = ((long)(b * 192 + y) * 192 + xg) * 8;
        const uint4* sh = (const uint4*)g_x_hi + base;
        const uint4 z = make_uint4(0, 0, 0, 0);
#pragma unroll
        for (int c = 0; c < 8; ++c) {
            uint32_t off = (uint32_t)hr * 128u + (uint32_t)((c ^ (hr & 7)) << 4);
            if (ok) {
                CP16(sbase + off, sh + c);
            } else {
                *(uint4*)(smem + off) = z;
            }
        }
    }
    prefetchB(0, 0);
    CP_COMMIT();
    CP_WAIT(0);
    __syncthreads();

    for (int tap = 0; tap < 9; ++tap) {
        if (tap < 8) {
            prefetchB(tap + 1, (tap + 1) & 1);
            CP_COMMIT();
        }

        const int dOff = (tap / 3 - 1) * 34 + (tap % 3 - 1);
        const uint32_t sbh = sbase + DB + (uint32_t)(tap & 1) * 8192u;

#pragma unroll
        for (int kc = 0; kc < 4; ++kc) {
            const int acol = kc * 2 + apart;
            const int bcol = kc * 2 + bpart;
            uint32_t bf[4][4], ah[4][4];
#pragma unroll
            for (int nt = 0; nt < 4; ++nt) {
                int row = brow0 + nt * 16;
                ldsm_x4(bf[nt], sbh + row * 128 + ((bcol ^ (row & 7)) << 4));
            }
#pragma unroll
            for (int mt = 0; mt < 4; ++mt) {
                int hr = hra[mt] + dOff;
                ldsm_x4(ah[mt], sbase + hr * 128 + ((acol ^ (hr & 7)) << 4));
            }
#pragma unroll
            for (int mt = 0; mt < 4; ++mt)
#pragma unroll
                for (int j = 0; j < 8; ++j)
                    mma_fp16(acc[mt][j], ah[mt], &bf[j >> 1][2 * (j & 1)]);
        }
        CP_WAIT(0);
        __syncthreads();
    }

    // epilogue: stage fp32 [m][oc] (stride 65), coalesced store
    float* st = (float*)smem;
#pragma unroll
    for (int mt = 0; mt < 4; ++mt)
#pragma unroll
        for (int j = 0; j < 8; ++j)
#pragma unroll
            for (int e = 0; e < 4; ++e) {
                int row = wid * 64 + mt * 16 + (lid >> 2) + ((e >> 1) << 3);
                int col = j * 8 + (lid & 3) * 2 + (e & 1);
                st[row * 65 + col] = acc[mt][j][e];
            }
    __syncthreads();

    for (int t = tid; t < 16384; t += 128) {
        int oc = t >> 8, m = t & 255;
        float v = fmaxf(st[m * 65 + oc], 0.f);
        out[((long)(b * 64 + oc) * 192 + (y0 + (m >> 5))) * 192 + x0 + (m & 31)] = v;
    }
}

// ---------------------------------------------------------------------------
// Launch
// ---------------------------------------------------------------------------
extern "C" void kernel_launch(void* const* d_in, const int* in_sizes, int n_in,
                              void* d_out, int out_size) {
    const float* x    = (const float*)d_in[0];  // (16,64,192,192)
    const float* w_qk = (const float*)d_in[1];  // (128,64,3,3)
    const float* wgt  = (const float*)d_in[2];  // (64,64,3,3)
    const float* temp = (const float*)d_in[3];  // (1,1,1)
    float* out = (float*)d_out;                 // (16,64,192,192)

    cudaFuncSetAttribute(qk_mma_kernel, cudaFuncAttributeMaxDynamicSharedMemorySize, QK_TOT);
    cudaFuncSetAttribute(attn_mma_kernel, cudaFuncAttributeMaxDynamicSharedMemorySize, AT_TOT);
    cudaFuncSetAttribute(final_mma_kernel, cudaFuncAttributeMaxDynamicSharedMemorySize, D_TOT);

    xcl_kernel<<<dim3(576, 17), 256>>>(x, w_qk, wgt);          // 0
    qk_mma_kernel<<<dim3(32, 2, 16), 128, QK_TOT>>>();         // 1
    attn_mma_kernel<<<dim3(25, 2, 16), 128, AT_TOT>>>();       // 2
    akconv_mma_kernel<<<dim3(9, 16), 128, 2 * AK_BUF>>>();     // 3
    kern_kernel<<<dim3(64, 16), 64>>>(wgt, temp);              // 4
    final_mma_kernel<<<dim3(6, 24, 16), 128, D_TOT>>>(out);    // 5 (ncu slot)
}

// round 17
// speedup vs baseline: 1.0339x; 1.0339x over previous
#include <cuda_runtime.h>
#include <cuda_fp16.h>
#include <cstdint>
#include <math.h>

// Problem constants
#define B_  16
#define C_  64
#define H_  192
#define W_  192
#define H2_ 64
#define W2_ 64
#define S_  5

// ---------------------------------------------------------------------------
// Scratch buffers (static device globals; zero-initialized at load)
// ---------------------------------------------------------------------------
__device__ float g_attnP[2][B_ * C_ * C_ * S_ * S_];  // 2 K-half partials
__device__ float g_ak[B_ * C_ * C_ * 9];              // transposed ak (pre-norm)

// fp16 operands (all single precision; fp32 staging between stages).
__device__ __align__(16) __half g_x_hi[B_ * H_ * W_ * C_];  // channel-last
__device__ __align__(16) __half g_kt[B_ * 9 * C_ * C_];     // [b][tap][oc][ci]
__device__ __align__(16) __half g_wq[2 * 9 * 64 * 64];      // [half][tap][oc][ci]
// attn A operand: k channel-major [b][co][4096]
__device__ __align__(16) __half g_k1[B_ * C_ * 4096];
// attn B operand: q shifted copies [dj(5)][b][ci][68 rows (zero-pad)][64]
__device__ __align__(16) __half g_q5[5 * B_ * C_ * 68 * 64];

__device__ __forceinline__ uint32_t smem_u32(const void* p) {
    uint32_t a;
    asm("{ .reg .u64 t; cvta.to.shared.u64 t, %1; cvt.u32.u64 %0, t; }" : "=r"(a) : "l"(p));
    return a;
}

__device__ __forceinline__ void ldsm_x4(uint32_t* r, uint32_t addr) {
    asm volatile("ldmatrix.sync.aligned.m8n8.x4.shared.b16 {%0,%1,%2,%3}, [%4];"
                 : "=r"(r[0]), "=r"(r[1]), "=r"(r[2]), "=r"(r[3])
                 : "r"(addr));
}

// mma.sync m16n8k16 fp16 -> fp32 accum (in-place)
__device__ __forceinline__ void mma_fp16(float* d, const uint32_t* a, const uint32_t* b) {
    asm volatile(
        "mma.sync.aligned.m16n8k16.row.col.f32.f16.f16.f32 "
        "{%0,%1,%2,%3}, {%4,%5,%6,%7}, {%8,%9}, {%0,%1,%2,%3};"
        : "+f"(d[0]), "+f"(d[1]), "+f"(d[2]), "+f"(d[3])
        : "r"(a[0]), "r"(a[1]), "r"(a[2]), "r"(a[3]), "r"(b[0]), "r"(b[1]));
}

#define CP16(dst, src) \
    asm volatile("cp.async.cg.shared.global [%0], [%1], 16;" ::"r"(dst), "l"(src))
#define CP_COMMIT() asm volatile("cp.async.commit_group;" ::: "memory")
#define CP_WAIT(N) asm volatile("cp.async.wait_group %0;" ::"n"(N) : "memory")

// ---------------------------------------------------------------------------
// Kernel E0: x (fp32 NCHW) -> channel-last fp16; b==16 repacks w_qk.
// ---------------------------------------------------------------------------
__global__ void __launch_bounds__(256) xcl_kernel(const float* __restrict__ x,
                                                  const float* __restrict__ w_qk) {
    const int seg = blockIdx.x;
    const int b = blockIdx.y;
    const int tid = threadIdx.x;

    if (b == 16) {
        if (seg < 128) {
            const int half = seg >> 6, oc = seg & 63;
            for (int t = tid; t < 576; t += 256) {
                int ci = t / 9, tap = t % 9;
                g_wq[((half * 9 + tap) * 64 + oc) * 64 + ci] =
                    __float2half(w_qk[(seg * 64 + ci) * 9 + tap]);
            }
        }
        return;
    }

    const int y = seg / 3;
    const int x0 = (seg % 3) * 64;
    __shared__ float s[64][65];

#pragma unroll
    for (int i = 0; i < 16; ++i) {
        int idx = tid + i * 256;
        int c = idx >> 6, p = idx & 63;
        s[p][c] = x[((b * 64 + c) * 192 + y) * 192 + x0 + p];
    }
    __syncthreads();
#pragma unroll
    for (int i = 0; i < 16; ++i) {
        int idx = tid + i * 256;
        int p = idx >> 6, c = idx & 63;
        g_x_hi[((b * 192 + y) * 192 + x0 + p) * 64 + c] = __float2half(s[p][c]);
    }
}

// ---------------------------------------------------------------------------
// Kernel A: qk conv via mma.sync (stride-3), cp.async tap double-buffer.
// FUSED epilogue: k -> g_k1, q -> g_q5 (5 dj copies).
// grid (32 mtiles, 2 half, 16 b), 128 thr. smem 2 x 24KB.
// ---------------------------------------------------------------------------
#define QK_B    16384
#define QK_BUF  24576
#define QK_TOT  49152

__global__ void __launch_bounds__(128) qk_mma_kernel() {
    extern __shared__ char smem[];
    const int mtile = blockIdx.x, half = blockIdx.y, b = blockIdx.z;
    const int i0 = mtile * 2;
    const int tid = threadIdx.x, wid = tid >> 5, lid = tid & 31;
    const uint32_t sbase = smem_u32(smem);

    const int r = tid;
    const int ri = i0 + (r >> 6), rj = r & 63;

    float acc[2][8][4];
#pragma unroll
    for (int mt = 0; mt < 2; ++mt)
#pragma unroll
        for (int j = 0; j < 8; ++j)
#pragma unroll
            for (int e = 0; e < 4; ++e) acc[mt][j][e] = 0.f;

    const int arow0 = wid * 32 + (lid & 15);
    const int apart = lid >> 4;
    const int brow0 = (lid & 7) + ((lid >> 4) << 3);
    const int bpart = (lid >> 3) & 1;

    auto prefetch = [&](int tap, int bi) {
        uint32_t sb = sbase + (uint32_t)bi * QK_BUF;
        const int dy = tap / 3, dx = tap % 3;
        long abase = ((long)(b * 192 + 3 * ri + dy) * 192 + 3 * rj + dx) * 8;
        const uint4* sh = (const uint4*)g_x_hi + abase;
#pragma unroll
        for (int c = 0; c < 8; ++c) {
            uint32_t off = (uint32_t)r * 128u + (uint32_t)((c ^ (r & 7)) << 4);
            CP16(sb + off, sh + c);
        }
        const uint4* wp = (const uint4*)g_wq + (half * 9 + tap) * 512;
#pragma unroll
        for (int i = 0; i < 4; ++i) {
            int idx = tid + i * 128;
            int row = idx >> 3, c = idx & 7;
            uint32_t off = (uint32_t)row * 128u + (uint32_t)((c ^ (row & 7)) << 4);
            CP16(sb + QK_B + off, wp + idx);
        }
    };

    prefetch(0, 0);
    CP_COMMIT();

    for (int tap = 0; tap < 9; ++tap) {
        if (tap < 8) {
            prefetch(tap + 1, (tap + 1) & 1);
            CP_COMMIT();
            CP_WAIT(1);
        } else {
            CP_WAIT(0);
        }
        __syncthreads();

        const uint32_t sb = sbase + (uint32_t)(tap & 1) * QK_BUF;
#pragma unroll
        for (int kc = 0; kc < 4; ++kc) {
            const int acol = kc * 2 + apart;
            const int bcol = kc * 2 + bpart;
            uint32_t bf[4][4], ah[2][4];
#pragma unroll
            for (int nt = 0; nt < 4; ++nt) {
                int row = brow0 + nt * 16;
                ldsm_x4(bf[nt], sb + QK_B + row * 128 + ((bcol ^ (row & 7)) << 4));
            }
#pragma unroll
            for (int mt = 0; mt < 2; ++mt) {
                int row = arow0 + mt * 16;
                ldsm_x4(ah[mt], sb + row * 128 + ((acol ^ (row & 7)) << 4));
            }
#pragma unroll
            for (int mt = 0; mt < 2; ++mt)
#pragma unroll
                for (int j = 0; j < 8; ++j)
                    mma_fp16(acc[mt][j], ah[mt], &bf[j >> 1][2 * (j & 1)]);
        }
        __syncthreads();
    }

    // ---- fused epilogue: stage fp32 [m][ch] (stride 65), emit fp16 operands
    float* st = (float*)smem;
#pragma unroll
    for (int mt = 0; mt < 2; ++mt)
#pragma unroll
        for (int j = 0; j < 8; ++j)
#pragma unroll
            for (int e = 0; e < 4; ++e) {
                int m = wid * 32 + mt * 16 + (lid >> 2) + ((e >> 1) << 3);
                int col = j * 8 + (lid & 3) * 2 + (e & 1);
                st[m * 65 + col] = acc[mt][j][e];
            }
    __syncthreads();

    if (half) {
        for (int t = tid; t < 8192; t += 128) {
            int co = t >> 7, m = t & 127;
            int h = i0 + (m >> 6), w = m & 63;
            long o = (long)(b * 64 + co) * 4096 + h * 64 + w;
            g_k1[o] = __float2half(st[m * 65 + co]);
        }
    } else {
        for (int dj = 0; dj < 5; ++dj) {
            for (int t = tid; t < 8192; t += 128) {
                int ci = t >> 7, m = t & 127;
                int h = i0 + (m >> 6), w = m & 63;
                int wsrc = w + dj - 2;
                float v = ((unsigned)wsrc < 64u) ? st[((m >> 6) * 64 + wsrc) * 65 + ci] : 0.f;
                long o = (((long)(dj * 16 + b) * 64 + ci) * 68 + (h + 2)) * 64 + w;
                g_q5[o] = __float2half(v);
            }
        }
    }
}

// ---------------------------------------------------------------------------
// Kernel B: attn via mma.sync, K SPLIT IN 2. grid (25, 2, 16), 128 thr.
// ---------------------------------------------------------------------------
#define AT_Q   8192
#define AT_BUF 16384
#define AT_TOT 32768

__global__ void __launch_bounds__(128) attn_mma_kernel() {
    extern __shared__ char smem[];
    const int dj = blockIdx.x % 5, di = blockIdx.x / 5;
    const int half = blockIdx.y, b = blockIdx.z;
    const int tid = threadIdx.x, wid = tid >> 5, lid = tid & 31;
    const uint32_t sbase = smem_u32(smem);
    const int mrow = (wid & 1) * 32, ncol = (wid >> 1) * 32;

    float acc[2][4][4];
#pragma unroll
    for (int mt = 0; mt < 2; ++mt)
#pragma unroll
        for (int j = 0; j < 4; ++j)
#pragma unroll
            for (int e = 0; e < 4; ++e) acc[mt][j][e] = 0.f;

    const uint4* __restrict__ kp = (const uint4*)g_k1 + (long)b * 64 * 512;
    const uint4* __restrict__ qp = (const uint4*)g_q5 + (long)(dj * 16 + b) * 64 * 544 + di * 8;

    const int apart = lid >> 4;
    const int brow_l = (lid & 7) + ((lid >> 4) << 3);
    const int bpart = (lid >> 3) & 1;
    const int kc0 = half * 32;

    auto prefetch = [&](int kc, int bi) {
        uint32_t sb = sbase + (uint32_t)bi * AT_BUF;
#pragma unroll
        for (int a = 0; a < 2; ++a) {
            const uint4* gp = (a == 0) ? kp : qp;
            const int stride = (a == 0) ? 512 : 544;
#pragma unroll
            for (int u = 0; u < 4; ++u) {
                int idx = tid + u * 128;
                int row = idx >> 3, c = idx & 7;
                uint32_t off = (uint32_t)a * 8192u + (uint32_t)row * 128u +
                               (uint32_t)((c ^ (row & 7)) << 4);
                CP16(sb + off, gp + (long)row * stride + kc * 8 + c);
            }
        }
    };

    prefetch(kc0, 0);
    CP_COMMIT();

    for (int kc2 = 0; kc2 < 32; ++kc2) {
        if (kc2 < 31) {
            prefetch(kc0 + kc2 + 1, (kc2 + 1) & 1);
            CP_COMMIT();
            CP_WAIT(1);
        } else {
            CP_WAIT(0);
        }
        __syncthreads();

        const uint32_t sb = sbase + (uint32_t)(kc2 & 1) * AT_BUF;
#pragma unroll
        for (int kk = 0; kk < 4; ++kk) {
            uint32_t ah[2][4], bh[2][4];
            const int acol = kk * 2 + apart;
            const int bcol = kk * 2 + bpart;
#pragma unroll
            for (int mt = 0; mt < 2; ++mt) {
                int row = mrow + mt * 16 + (lid & 15);
                ldsm_x4(ah[mt], sb + row * 128 + ((acol ^ (row & 7)) << 4));
            }
#pragma unroll
            for (int nt = 0; nt < 2; ++nt) {
                int row = ncol + nt * 16 + brow_l;
                ldsm_x4(bh[nt], sb + AT_Q + row * 128 + ((bcol ^ (row & 7)) << 4));
            }
#pragma unroll
            for (int mt = 0; mt < 2; ++mt)
#pragma unroll
                for (int j = 0; j < 4; ++j)
                    mma_fp16(acc[mt][j], ah[mt], &bh[j >> 1][2 * (j & 1)]);
        }
        __syncthreads();
    }

    float* dst = g_attnP[half];
#pragma unroll
    for (int mt = 0; mt < 2; ++mt)
#pragma unroll
        for (int j = 0; j < 4; ++j)
#pragma unroll
            for (int e = 0; e < 4; ++e) {
                int co = mrow + mt * 16 + (lid >> 2) + ((e >> 1) << 3);
                int ci = ncol + j * 8 + (lid & 3) * 2 + (e & 1);
                dst[((b * 64 + co) * 64 + ci) * 25 + di * 5 + dj] = acc[mt][j][e];
            }
}

// ---------------------------------------------------------------------------
// Kernel C1: ak conv (VALID 3x3 over 5x5 attn), scalar (measured-best config).
// grid (16 cAg, 16 b), 256 thr = 4 cA x 64 cB. Sums 2 K-half partials.
// ---------------------------------------------------------------------------
__global__ void __launch_bounds__(256) akconv_kernel(const float* __restrict__ weight) {
    const int cAg = blockIdx.x;
    const int b   = blockIdx.y;
    const int tid = threadIdx.x;
    const int s  = tid >> 6;
    const int cB = tid & 63;
    const int cA = cAg * 4 + s;

    __shared__ float as4[4][64][25];
    __shared__ float ws[64][73];

    for (int t = tid; t < 6400; t += 256) {
        int a = t / 1600, r = t % 1600;
        long o = (long)(b * 64 + cAg * 4 + a) * 1600 + r;
        as4[a][r / 25][r % 25] = g_attnP[0][o] + g_attnP[1][o];
    }

    float acc[9];
#pragma unroll
    for (int t9 = 0; t9 < 9; ++t9) acc[t9] = 0.f;

    for (int cic = 0; cic < 8; ++cic) {
        __syncthreads();
        for (int t = tid; t < 4608; t += 256) {
            int c2 = t / 72;
            int rr = t % 72;
            ws[c2][rr] = weight[c2 * 576 + (cic * 8 + rr / 9) * 9 + (rr % 9)];
        }
        __syncthreads();
#pragma unroll
        for (int ci = 0; ci < 8; ++ci) {
            float av[25];
#pragma unroll
            for (int p = 0; p < 25; ++p) av[p] = as4[s][cic * 8 + ci][p];
#pragma unroll
            for (int dy = 0; dy < 3; ++dy)
#pragma unroll
                for (int dx = 0; dx < 3; ++dx) {
                    float wv = ws[cB][ci * 9 + dy * 3 + dx];
#pragma unroll
                    for (int ky = 0; ky < 3; ++ky)
#pragma unroll
                        for (int kx = 0; kx < 3; ++kx)
                            acc[ky * 3 + kx] =
                                fmaf(av[(ky + dy) * 5 + (kx + dx)], wv, acc[ky * 3 + kx]);
                }
        }
    }
#pragma unroll
    for (int t9 = 0; t9 < 9; ++t9)
        g_ak[((b * 64 + cB) * 64 + cA) * 9 + t9] = acc[t9];
}

// ---------------------------------------------------------------------------
// Kernel C2: normalize ak, build dynamic kernels -> single fp16 B tiles
// ---------------------------------------------------------------------------
__global__ void __launch_bounds__(64) kern_kernel(const float* __restrict__ weight,
                                                  const float* __restrict__ temperature) {
    const int cB  = blockIdx.x;
    const int b   = blockIdx.y;
    const int tid = threadIdx.x;  // = cA

    const float* ak = g_ak + (b * 64 + cB) * 64 * 9;
    float v[9];
    float ss = 0.f;
#pragma unroll
    for (int t9 = 0; t9 < 9; ++t9) {
        v[t9] = ak[tid * 9 + t9];
        ss = fmaf(v[t9], v[t9], ss);
    }

    __shared__ float red[64];
    red[tid] = ss;
    __syncthreads();
#pragma unroll
    for (int s = 32; s >= 1; s >>= 1) {
        if (tid < s) red[tid] += red[tid + s];
        __syncthreads();
    }
    float nrm = sqrtf(red[0]);
    float scale = temperature[0] / fmaxf(nrm, 1e-12f);

#pragma unroll
    for (int t9 = 0; t9 < 9; ++t9) {
        float vv = weight[(cB * 64 + tid) * 9 + t9] + v[t9] * scale;
        g_kt[((b * 9 + t9) * 64 + cB) * 64 + tid] = __float2half(vv);
    }
}

// ---------------------------------------------------------------------------
// Kernel D: final conv via mma.sync, M=256 (8y x 32x), 128 thr, warp m=64.
// smem: A halo 340x128=43520 | B 2x8192; epilogue needs 256*65*4=66560.
// ---------------------------------------------------------------------------
#define DB     43520
#define D_TOT  66560

__global__ void __launch_bounds__(128) final_mma_kernel(float* __restrict__ out) {
    extern __shared__ char smem[];
    const int xt = blockIdx.x, yp = blockIdx.y, b = blockIdx.z;
    const int x0 = xt * 32, y0 = yp * 8;
    const int tid = threadIdx.x, wid = tid >> 5, lid = tid & 31;
    const uint32_t sbase = smem_u32(smem);

    float acc[4][8][4];
#pragma unroll
    for (int mt = 0; mt < 4; ++mt)
#pragma unroll
        for (int j = 0; j < 8; ++j)
#pragma unroll
            for (int e = 0; e < 4; ++e) acc[mt][j][e] = 0.f;

    const int apart = lid >> 4;
    const int brow0 = (lid & 7) + ((lid >> 4) << 3);
    const int bpart = (lid >> 3) & 1;
    int hra[4];
#pragma unroll
    for (int mt = 0; mt < 4; ++mt) {
        int m = wid * 64 + mt * 16 + (lid & 15);
        hra[mt] = ((m >> 5) + 1) * 34 + (m & 31) + 1;
    }

    auto prefetchB = [&](int tap, int bi) {
        uint32_t sb = sbase + DB + (uint32_t)bi * 8192u;
        const uint4* kp = (const uint4*)g_kt + (b * 9 + tap) * 512;
#pragma unroll
        for (int u = 0; u < 4; ++u) {
            int idx = tid + u * 128;
            int row = idx >> 3, c = idx & 7;
            uint32_t off = (uint32_t)row * 128u + (uint32_t)((c ^ (row & 7)) << 4);
            CP16(sb + off, kp + idx);
        }
    };

    // ---- one-time A halo fill (340 rows = 10y x 34x) + B tap0 ----
    for (int hr = tid; hr < 340; hr += 128) {
        int hy = hr / 34, hx = hr % 34;
        int y = y0 - 1 + hy, xg = x0 - 1 + hx;
        bool ok = ((unsigned)y < (unsigned)H_) && ((unsigned)xg < (unsigned)W_);
        long base = ((long)(b * 192 + y) * 192 + xg) * 8;
        const uint4* sh = (const uint4*)g_x_hi + base;
        const uint4 z = make_uint4(0, 0, 0, 0);
#pragma unroll
        for (int c = 0; c < 8; ++c) {
            uint32_t off = (uint32_t)hr * 128u + (uint32_t)((c ^ (hr & 7)) << 4);
            if (ok) {
                CP16(sbase + off, sh + c);
            } else {
                *(uint4*)(smem + off) = z;
            }
        }
    }
    prefetchB(0, 0);
    CP_COMMIT();
    CP_WAIT(0);
    __syncthreads();

    for (int tap = 0; tap < 9; ++tap) {
        if (tap < 8) {
            prefetchB(tap + 1, (tap + 1) & 1);
            CP_COMMIT();
        }

        const int dOff = (tap / 3 - 1) * 34 + (tap % 3 - 1);
        const uint32_t sbh = sbase + DB + (uint32_t)(tap & 1) * 8192u;

#pragma unroll
        for (int kc = 0; kc < 4; ++kc) {
            const int acol = kc * 2 + apart;
            const int bcol = kc * 2 + bpart;
            uint32_t bf[4][4], ah[4][4];
#pragma unroll
            for (int nt = 0; nt < 4; ++nt) {
                int row = brow0 + nt * 16;
                ldsm_x4(bf[nt], sbh + row * 128 + ((bcol ^ (row & 7)) << 4));
            }
#pragma unroll
            for (int mt = 0; mt < 4; ++mt) {
                int hr = hra[mt] + dOff;
                ldsm_x4(ah[mt], sbase + hr * 128 + ((acol ^ (hr & 7)) << 4));
            }
#pragma unroll
            for (int mt = 0; mt < 4; ++mt)
#pragma unroll
                for (int j = 0; j < 8; ++j)
                    mma_fp16(acc[mt][j], ah[mt], &bf[j >> 1][2 * (j & 1)]);
        }
        CP_WAIT(0);
        __syncthreads();
    }

    // epilogue: stage fp32 [m][oc] (stride 65), coalesced store
    float* st = (float*)smem;
#pragma unroll
    for (int mt = 0; mt < 4; ++mt)
#pragma unroll
        for (int j = 0; j < 8; ++j)
#pragma unroll
            for (int e = 0; e < 4; ++e) {
                int row = wid * 64 + mt * 16 + (lid >> 2) + ((e >> 1) << 3);
                int col = j * 8 + (lid & 3) * 2 + (e & 1);
                st[row * 65 + col] = acc[mt][j][e];
            }
    __syncthreads();

    for (int t = tid; t < 16384; t += 128) {
        int oc = t >> 8, m = t & 255;
        float v = fmaxf(st[m * 65 + oc], 0.f);
        out[((long)(b * 64 + oc) * 192 + (y0 + (m >> 5))) * 192 + x0 + (m & 31)] = v;
    }
}

// ---------------------------------------------------------------------------
// Launch
// ---------------------------------------------------------------------------
extern "C" void kernel_launch(void* const* d_in, const int* in_sizes, int n_in,
                              void* d_out, int out_size) {
    const float* x    = (const float*)d_in[0];  // (16,64,192,192)
    const float* w_qk = (const float*)d_in[1];  // (128,64,3,3)
    const float* wgt  = (const float*)d_in[2];  // (64,64,3,3)
    const float* temp = (const float*)d_in[3];  // (1,1,1)
    float* out = (float*)d_out;                 // (16,64,192,192)

    cudaFuncSetAttribute(qk_mma_kernel, cudaFuncAttributeMaxDynamicSharedMemorySize, QK_TOT);
    cudaFuncSetAttribute(attn_mma_kernel, cudaFuncAttributeMaxDynamicSharedMemorySize, AT_TOT);
    cudaFuncSetAttribute(final_mma_kernel, cudaFuncAttributeMaxDynamicSharedMemorySize, D_TOT);

    xcl_kernel<<<dim3(576, 17), 256>>>(x, w_qk);               // 0
    qk_mma_kernel<<<dim3(32, 2, 16), 128, QK_TOT>>>();         // 1
    attn_mma_kernel<<<dim3(25, 2, 16), 128, AT_TOT>>>();       // 2
    akconv_kernel<<<dim3(16, 16), 256>>>(wgt);                 // 3
    kern_kernel<<<dim3(64, 16), 64>>>(wgt, temp);              // 4
    final_mma_kernel<<<dim3(6, 24, 16), 128, D_TOT>>>(out);    // 5 (ncu slot)
}